// round 16
// baseline (speedup 1.0000x reference)
#include <cuda_runtime.h>
#include <cstdint>

#define C        128
#define KNB      16
#define M        16            // points per block tile
#define NPTS     (8*4096)
#define NTASK    (NPTS/M)      // 2048
#define RS       132           // padded smem row stride (floats)

// Warp-blocked MMA fragment weight layout (m16n8k8 tf32):
// float4 at [(n0*16 + k0)*32 + lane] (lane = g*4 + t) holds
//   .x = hi(W[n0*8+g][k0*8+t])  .y = hi(...t+4)  .z = lo(...t)  .w = lo(...t+4)
__device__ float4 g_Bf[C*C/2];   // W = fold * B^T (n=logit ch, k=input ch)
__device__ float4 g_Wf[C*C/2];   // W = wv (n=output ch, k=input ch)

__device__ __forceinline__ uint32_t tf32hi(float x) {
    uint32_t r; asm("cvt.rna.tf32.f32 %0, %1;" : "=r"(r) : "f"(x)); return r;
}
__device__ __forceinline__ float ex2(float x) {
    float r; asm("ex2.approx.f32 %0, %1;" : "=f"(r) : "f"(x)); return r;
}
__device__ __forceinline__ float dot4(const float4 a, const float4 b) {
    float t = a.x * b.x;
    t = fmaf(a.y, b.y, t);
    t = fmaf(a.z, b.z, t);
    t = fmaf(a.w, b.w, t);
    return t;
}
__device__ __forceinline__ void mma8(float* d, const uint32_t* a,
                                     uint32_t b0, uint32_t b1) {
    asm volatile("mma.sync.aligned.m16n8k8.row.col.f32.tf32.tf32.f32 "
                 "{%0,%1,%2,%3}, {%4,%5,%6,%7}, {%8,%9}, {%0,%1,%2,%3};"
                 : "+f"(d[0]), "+f"(d[1]), "+f"(d[2]), "+f"(d[3])
                 : "r"(a[0]), "r"(a[1]), "r"(a[2]), "r"(a[3]),
                   "r"(b0), "r"(b1));
}

__global__ void precompute_kernel(const float* __restrict__ wq,
                                  const float* __restrict__ wk,
                                  const float* __restrict__ wv) {
    const int i = blockIdx.x;   // input channel (k)
    const int j = threadIdx.x;  // output channel (n)
    float acc = 0.f;
#pragma unroll
    for (int o = 0; o < 64; ++o)
        acc = fmaf(wq[o*C + i], wk[o*C + j], acc);
    acc *= (0.125f * 1.4426950408889634f);     // fold softmax scale + log2(e)

    const int n0 = j >> 3, g = j & 7;
    const int k0 = i >> 3, kk = i & 7;
    const int t  = kk & 3, pos = kk >> 2;      // pos 0 -> (x,z), 1 -> (y,w)
    const int base = (((n0*16 + k0)*32) + (g*4 + t)) * 4;

    const uint32_t bh = tf32hi(acc);
    ((float*)g_Bf)[base + pos]     = __uint_as_float(bh);
    ((float*)g_Bf)[base + 2 + pos] = acc - __uint_as_float(bh);
    const float w = wv[j*C + i];
    const uint32_t wh = tf32hi(w);
    ((float*)g_Wf)[base + pos]     = __uint_as_float(wh);
    ((float*)g_Wf)[base + 2 + pos] = w - __uint_as_float(wh);
}

// Split-N 3xTF32 block GEMM step: D[16x128] = A(sa) * W^T, warp w owns
// n0-blocks [4w, 4w+4). Result fragments written to sd.
__device__ __forceinline__ void gemm_block(const float* __restrict__ sa,
                                           float* __restrict__ sd,
                                           const float4* __restrict__ wfw,
                                           int warp, int g, int t, int lane) {
    float acc[4][4];
#pragma unroll
    for (int n = 0; n < 4; ++n)
#pragma unroll
        for (int q = 0; q < 4; ++q) acc[n][q] = 0.f;

#pragma unroll 1
    for (int k0 = 0; k0 < 16; ++k0) {
        // independent weight loads first (deep MLP)
        const float4* wp = wfw + k0*32 + lane;
        const float4 b0 = wp[0*512];
        const float4 b1 = wp[1*512];
        const float4 b2 = wp[2*512];
        const float4 b3 = wp[3*512];

        // A fragment (tf32 m16n8k8): a0=(g,t) a1=(g+8,t) a2=(g,t+4) a3=(g+8,t+4)
        const float a0 = sa[g*RS     + k0*8 + t];
        const float a1 = sa[(g+8)*RS + k0*8 + t];
        const float a2 = sa[g*RS     + k0*8 + t + 4];
        const float a3 = sa[(g+8)*RS + k0*8 + t + 4];
        uint32_t ah[4], al[4];
        ah[0] = tf32hi(a0); ah[1] = tf32hi(a1);
        ah[2] = tf32hi(a2); ah[3] = tf32hi(a3);
        al[0] = __float_as_uint(a0 - __uint_as_float(ah[0]));
        al[1] = __float_as_uint(a1 - __uint_as_float(ah[1]));
        al[2] = __float_as_uint(a2 - __uint_as_float(ah[2]));
        al[3] = __float_as_uint(a3 - __uint_as_float(ah[3]));

        const float4 bb[4] = {b0, b1, b2, b3};
#pragma unroll
        for (int n = 0; n < 4; ++n) {
            const uint32_t bh0 = __float_as_uint(bb[n].x);
            const uint32_t bh1 = __float_as_uint(bb[n].y);
            mma8(acc[n], ah, bh0, bh1);
            mma8(acc[n], al, bh0, bh1);
            mma8(acc[n], ah, __float_as_uint(bb[n].z), __float_as_uint(bb[n].w));
        }
    }

    // C fragment -> smem: c0=(g,2t) c1=(g,2t+1) c2=(g+8,2t) c3=(g+8,2t+1)
#pragma unroll
    for (int n = 0; n < 4; ++n) {
        const int col = (warp*4 + n)*8 + 2*t;
        *(float2*)(sd + g*RS     + col) = make_float2(acc[n][0], acc[n][1]);
        *(float2*)(sd + (g+8)*RS + col) = make_float2(acc[n][2], acc[n][3]);
    }
}

// Fused: gemm-A -> softmax middle -> gemm-C, one block per 16-point tile.
__global__ void __launch_bounds__(128, 4)
attn_fused_kernel(const float* __restrict__ fc,   // [NPTS][C]
                  const float* __restrict__ fn,   // [NPTS][KNB][C]
                  float* __restrict__ outp)       // [NPTS][C]
{
    __shared__ __align__(16) float sx[M*RS];   // X tile -> Y tile
    __shared__ __align__(16) float su[M*RS];   // U tile -> Out tile

    const int warp = threadIdx.x >> 5;
    const int lane = threadIdx.x & 31;
    const int p0 = blockIdx.x * M;
    const int g = lane >> 2, t = lane & 3;
    const int l4 = lane * 4;

    // ---- stage X (center features) ----
#pragma unroll
    for (int it = 0; it < 4; ++it) {
        const int r = warp*4 + it;
        *(float4*)(sx + r*RS + l4) =
            *(const float4*)(fc + (size_t)(p0 + r)*C + l4);
    }
    __syncthreads();

    // ---- GEMM-A: U = X * B^T ----
    gemm_block(sx, su, g_Bf + (warp*4)*512, warp, g, t, lane);
    __syncthreads();

    // ---- middle: warp handles points [4*warp, 4*warp+4) ----
#pragma unroll 1
    for (int pp = 0; pp < 4; ++pp) {
        const int p = warp*4 + pp;
        const float4 u4 = *(const float4*)(su + p*RS + l4);
        const float4 c4 = *(const float4*)(sx + p*RS + l4);
        const float* xn = fn + (size_t)(p0 + p)*(KNB*C) + l4;

        float4 xr[KNB];
#pragma unroll
        for (int j = 0; j < KNB; ++j)
            xr[j] = *(const float4*)(xn + j*C);

        float d[KNB + 1];
#pragma unroll
        for (int j = 0; j < KNB; ++j) d[j] = dot4(u4, xr[j]);
        d[KNB] = dot4(u4, c4);
#pragma unroll
        for (int off = 16; off; off >>= 1)
#pragma unroll
            for (int q = 0; q <= KNB; ++q)
                d[q] += __shfl_xor_sync(0xffffffffu, d[q], off);

        float m = d[0];
#pragma unroll
        for (int q = 1; q <= KNB; ++q) m = fmaxf(m, d[q]);
        const float wc = ex2(d[KNB] - m);
        float s = wc;
        float4 y;
        y.x = wc*c4.x; y.y = wc*c4.y; y.z = wc*c4.z; y.w = wc*c4.w;
#pragma unroll
        for (int j = 0; j < KNB; ++j) {
            const float w = ex2(d[j] - m);
            s += w;
            y.x = fmaf(w, xr[j].x, y.x);
            y.y = fmaf(w, xr[j].y, y.y);
            y.z = fmaf(w, xr[j].z, y.z);
            y.w = fmaf(w, xr[j].w, y.w);
        }
        const float rs = __fdividef(1.f, s);
        y.x *= rs; y.y *= rs; y.z *= rs; y.w *= rs;
        *(float4*)(sx + p*RS + l4) = y;    // overwrite X row with Y row
    }
    __syncthreads();

    // ---- GEMM-C: Out = Y * wv^T ----
    gemm_block(sx, su, g_Wf + (warp*4)*512, warp, g, t, lane);
    __syncthreads();

    // ---- coalesced store ----
#pragma unroll
    for (int it = 0; it < 4; ++it) {
        const int r = warp*4 + it;
        *(float4*)(outp + (size_t)(p0 + r)*C + l4) =
            *(const float4*)(su + r*RS + l4);
    }
}

extern "C" void kernel_launch(void* const* d_in, const int* in_sizes, int n_in,
                              void* d_out, int out_size) {
    const float* fc = (const float*)d_in[0];   // fea_center [8,4096,1,128]
    const float* fn = (const float*)d_in[1];   // fea_near   [8,4096,16,128]
    const float* wq = (const float*)d_in[2];   // [64,128]
    const float* wk = (const float*)d_in[3];   // [64,128]
    const float* wv = (const float*)d_in[4];   // [128,128]
    float* out = (float*)d_out;                // [8,4096,128]

    precompute_kernel<<<C, C>>>(wq, wk, wv);
    attn_fused_kernel<<<NTASK, 128>>>(fc, fn, out);
}

// round 17
// speedup vs baseline: 1.0689x; 1.0689x over previous
#include <cuda_runtime.h>
#include <cstdint>

#define C        128
#define KNB      16
#define MG       32            // points per gemm block (two m16 tiles)
#define NPTS     (8*4096)
#define NGBLK    (NPTS/MG)     // 1024
#define RS       132           // padded smem row stride (floats)
#define P2       4             // points per warp (middle kernel)
#define MIDW     8             // warps per middle block

// Warp-blocked MMA fragment weight layout (m16n8k8 tf32):
// float4 at [(n0*16 + k0)*32 + lane] (lane = g*4 + t) holds
//   .x = hi(W[n0*8+g][k0*8+t])  .y = hi(...t+4)  .z = lo(...t)  .w = lo(...t+4)
__device__ float4 g_Bf[C*C/2];   // W = fold * B^T (n=logit ch, k=input ch)
__device__ float4 g_Wf[C*C/2];   // W = wv (n=output ch, k=input ch)
__device__ float  g_U[NPTS*C];   // scratch: logit-projection of centers (16 MB)
__device__ float  g_Y[NPTS*C];   // scratch: softmax-weighted features (16 MB)

__device__ __forceinline__ uint32_t tf32hi(float x) {
    uint32_t r; asm("cvt.rna.tf32.f32 %0, %1;" : "=r"(r) : "f"(x)); return r;
}
__device__ __forceinline__ float ex2(float x) {
    float r; asm("ex2.approx.f32 %0, %1;" : "=f"(r) : "f"(x)); return r;
}
__device__ __forceinline__ float dot4(const float4 a, const float4 b) {
    float t = a.x * b.x;
    t = fmaf(a.y, b.y, t);
    t = fmaf(a.z, b.z, t);
    t = fmaf(a.w, b.w, t);
    return t;
}
__device__ __forceinline__ void mma8(float* d, const uint32_t* a,
                                     uint32_t b0, uint32_t b1) {
    asm volatile("mma.sync.aligned.m16n8k8.row.col.f32.tf32.tf32.f32 "
                 "{%0,%1,%2,%3}, {%4,%5,%6,%7}, {%8,%9}, {%0,%1,%2,%3};"
                 : "+f"(d[0]), "+f"(d[1]), "+f"(d[2]), "+f"(d[3])
                 : "r"(a[0]), "r"(a[1]), "r"(a[2]), "r"(a[3]),
                   "r"(b0), "r"(b1));
}

__global__ void precompute_kernel(const float* __restrict__ wq,
                                  const float* __restrict__ wk,
                                  const float* __restrict__ wv) {
    const int i = blockIdx.x;   // input channel (k)
    const int j = threadIdx.x;  // output channel (n)
    float acc = 0.f;
#pragma unroll
    for (int o = 0; o < 64; ++o)
        acc = fmaf(wq[o*C + i], wk[o*C + j], acc);
    acc *= (0.125f * 1.4426950408889634f);     // fold softmax scale + log2(e)

    const int n0 = j >> 3, g = j & 7;
    const int k0 = i >> 3, kk = i & 7;
    const int t  = kk & 3, pos = kk >> 2;      // pos 0 -> (x,z), 1 -> (y,w)
    const int base = (((n0*16 + k0)*32) + (g*4 + t)) * 4;

    const uint32_t bh = tf32hi(acc);
    ((float*)g_Bf)[base + pos]     = __uint_as_float(bh);
    ((float*)g_Bf)[base + 2 + pos] = acc - __uint_as_float(bh);
    const float w = wv[j*C + i];
    const uint32_t wh = tf32hi(w);
    ((float*)g_Wf)[base + pos]     = __uint_as_float(wh);
    ((float*)g_Wf)[base + 2 + pos] = w - __uint_as_float(wh);
}

// Split-N 3xTF32 GEMM over a 32-point tile: D[32x128] = A * W^T.
// Warp w owns n0-blocks [4w, 4w+4) for BOTH m16 tiles.
// mode 0: in = inp (fc),  W = g_Bf, out = g_U
// mode 1: in = g_Y,       W = g_Wf, out = outp
__global__ void __launch_bounds__(128, 5)
gemm_kernel(const float* __restrict__ inp, float* __restrict__ outp, int mode) {
    __shared__ __align__(16) float sx[MG*RS];
    __shared__ __align__(16) float su[MG*RS];

    const int warp = threadIdx.x >> 5;
    const int lane = threadIdx.x & 31;
    const int p0 = blockIdx.x * MG;
    const int g = lane >> 2, t = lane & 3;
    const int l4 = lane * 4;

    const float* in  = mode ? g_Y : inp;
    float* out       = mode ? outp : g_U;
    const float4* wf = (mode ? g_Wf : g_Bf) + (warp*4)*512;  // this warp's n0s

    // ---- stage A tile (each warp 8 rows) ----
#pragma unroll
    for (int it = 0; it < 8; ++it) {
        const int r = warp*8 + it;
        *(float4*)(sx + r*RS + l4) =
            *(const float4*)(in + (size_t)(p0 + r)*C + l4);
    }
    __syncthreads();

    float acc[2][4][4];
#pragma unroll
    for (int m = 0; m < 2; ++m)
#pragma unroll
        for (int n = 0; n < 4; ++n)
#pragma unroll
            for (int q = 0; q < 4; ++q) acc[m][n][q] = 0.f;

#pragma unroll 1
    for (int k0 = 0; k0 < 16; ++k0) {
        // independent weight loads first (deep MLP); reused by both m-tiles
        const float4* wp = wf + k0*32 + lane;
        const float4 bb[4] = { wp[0*512], wp[1*512], wp[2*512], wp[3*512] };

        // A fragments for both m16 tiles
        uint32_t ah[2][4], al[2][4];
#pragma unroll
        for (int m = 0; m < 2; ++m) {
            const int r0 = m*16 + g;
            const float a0 = sx[r0*RS     + k0*8 + t];
            const float a1 = sx[(r0+8)*RS + k0*8 + t];
            const float a2 = sx[r0*RS     + k0*8 + t + 4];
            const float a3 = sx[(r0+8)*RS + k0*8 + t + 4];
            ah[m][0] = tf32hi(a0); ah[m][1] = tf32hi(a1);
            ah[m][2] = tf32hi(a2); ah[m][3] = tf32hi(a3);
            al[m][0] = __float_as_uint(a0 - __uint_as_float(ah[m][0]));
            al[m][1] = __float_as_uint(a1 - __uint_as_float(ah[m][1]));
            al[m][2] = __float_as_uint(a2 - __uint_as_float(ah[m][2]));
            al[m][3] = __float_as_uint(a3 - __uint_as_float(ah[m][3]));
        }

#pragma unroll
        for (int n = 0; n < 4; ++n) {
            const uint32_t bh0 = __float_as_uint(bb[n].x);
            const uint32_t bh1 = __float_as_uint(bb[n].y);
            const uint32_t bl0 = __float_as_uint(bb[n].z);
            const uint32_t bl1 = __float_as_uint(bb[n].w);
#pragma unroll
            for (int m = 0; m < 2; ++m) {
                mma8(acc[m][n], ah[m], bh0, bh1);
                mma8(acc[m][n], al[m], bh0, bh1);
                mma8(acc[m][n], ah[m], bl0, bl1);
            }
        }
    }

    // C fragments -> smem: c0=(g,2t) c1=(g,2t+1) c2=(g+8,2t) c3=(g+8,2t+1)
#pragma unroll
    for (int m = 0; m < 2; ++m)
#pragma unroll
        for (int n = 0; n < 4; ++n) {
            const int col = (warp*4 + n)*8 + 2*t;
            const int r0 = m*16 + g;
            *(float2*)(su + r0*RS     + col) = make_float2(acc[m][n][0], acc[m][n][1]);
            *(float2*)(su + (r0+8)*RS + col) = make_float2(acc[m][n][2], acc[m][n][3]);
        }
    __syncthreads();

    // ---- coalesced store ----
#pragma unroll
    for (int it = 0; it < 8; ++it) {
        const int r = warp*8 + it;
        *(float4*)(out + (size_t)(p0 + r)*C + l4) =
            *(const float4*)(su + r*RS + l4);
    }
}

// Streaming softmax: reads fn/fc/g_U, writes g_Y. No smem, low regs.
__global__ void __launch_bounds__(MIDW*32, 2)
middle_kernel(const float* __restrict__ fc,
              const float* __restrict__ fn) {
    const int warp = threadIdx.x >> 5;
    const int lane = threadIdx.x & 31;
    const int l4 = lane * 4;
    const int p0 = (blockIdx.x * MIDW + warp) * P2;

#pragma unroll 1
    for (int pp = 0; pp < P2; ++pp) {
        const int p = p0 + pp;
        const float4 u4 = *(const float4*)(g_U + (size_t)p*C + l4);
        const float4 c4 = *(const float4*)(fc + (size_t)p*C + l4);
        const float* xn = fn + (size_t)p*(KNB*C) + l4;

        float4 xr[KNB];
#pragma unroll
        for (int j = 0; j < KNB; ++j)
            xr[j] = *(const float4*)(xn + j*C);

        float d[KNB + 1];
#pragma unroll
        for (int j = 0; j < KNB; ++j) d[j] = dot4(u4, xr[j]);
        d[KNB] = dot4(u4, c4);
#pragma unroll
        for (int off = 16; off; off >>= 1)
#pragma unroll
            for (int q = 0; q <= KNB; ++q)
                d[q] += __shfl_xor_sync(0xffffffffu, d[q], off);

        float m = d[0];
#pragma unroll
        for (int q = 1; q <= KNB; ++q) m = fmaxf(m, d[q]);
        const float wc = ex2(d[KNB] - m);
        float s = wc;
        float4 y;
        y.x = wc*c4.x; y.y = wc*c4.y; y.z = wc*c4.z; y.w = wc*c4.w;
#pragma unroll
        for (int j = 0; j < KNB; ++j) {
            const float w = ex2(d[j] - m);
            s += w;
            y.x = fmaf(w, xr[j].x, y.x);
            y.y = fmaf(w, xr[j].y, y.y);
            y.z = fmaf(w, xr[j].z, y.z);
            y.w = fmaf(w, xr[j].w, y.w);
        }
        const float rs = __fdividef(1.f, s);
        y.x *= rs; y.y *= rs; y.z *= rs; y.w *= rs;
        *(float4*)(g_Y + (size_t)p*C + l4) = y;
    }
}

extern "C" void kernel_launch(void* const* d_in, const int* in_sizes, int n_in,
                              void* d_out, int out_size) {
    const float* fc = (const float*)d_in[0];   // fea_center [8,4096,1,128]
    const float* fn = (const float*)d_in[1];   // fea_near   [8,4096,16,128]
    const float* wq = (const float*)d_in[2];   // [64,128]
    const float* wk = (const float*)d_in[3];   // [64,128]
    const float* wv = (const float*)d_in[4];   // [128,128]
    float* out = (float*)d_out;                // [8,4096,128]

    precompute_kernel<<<C, C>>>(wq, wk, wv);
    gemm_kernel<<<NGBLK, 128>>>(fc, out, 0);             // U = X * B^T
    middle_kernel<<<NPTS/(MIDW*P2), MIDW*32>>>(fc, fn);  // Y = softmax-avg
    gemm_kernel<<<NGBLK, 128>>>(fc, out, 1);             // Out = Y * wv^T
}